// round 1
// baseline (speedup 1.0000x reference)
#include <cuda_runtime.h>
#include <math.h>

#define BATCH 32
#define NTOK  1024
#define CDIM  256
#define DDIM  256
#define NSLOT 8
#define ROWS  (BATCH*NSLOT)   /* 256 */
#define NITER 3
#define ATTN_EPS 1e-8f
#define LN_EPS   1e-5f
#define SCALE    0.0625f      /* 256^-0.5 */

/* ------------------------ scratch (device globals) ------------------------ */
__device__ float g_X   [BATCH*NTOK*CDIM];   // LN(inputs)
__device__ float g_Km  [BATCH*NTOK*DDIM];   // keys
__device__ float g_Vm  [BATCH*NTOK*DDIM];   // values
__device__ float g_slots[ROWS*DDIM];
__device__ float g_snorm[ROWS*DDIM];
__device__ float g_q    [ROWS*DDIM];
__device__ float g_attn [BATCH*NSLOT*NTOK];
__device__ float g_rowsum[ROWS];
__device__ float g_upd  [ROWS*DDIM];
__device__ float g_gi   [ROWS*3*DDIM];
__device__ float g_gh   [ROWS*3*DDIM];
__device__ float g_t1   [ROWS*DDIM];
__device__ float g_t2   [ROWS*4*DDIM];

/* ------------------------------ small kernels ----------------------------- */
__global__ void slots_init_k(const float* __restrict__ mu,
                             const float* __restrict__ ls,
                             const float* __restrict__ noise) {
    int idx = blockIdx.x * 256 + threadIdx.x;      // 65536 total
    int dcol = idx & 255;
    g_slots[idx] = mu[dcol] + expf(ls[dcol]) * noise[idx];
}

__global__ void zero_rowsum_k() {
    g_rowsum[threadIdx.x] = 0.f;
}

__global__ void copy_out_k(float* __restrict__ out) {
    int idx = blockIdx.x * 256 + threadIdx.x;
    out[idx] = g_slots[idx];
}

/* LayerNorm over last dim (=256). One block per row, 256 threads. */
__global__ void ln_rows_k(const float* __restrict__ in, float* __restrict__ out,
                          const float* __restrict__ gam, const float* __restrict__ bet) {
    int row = blockIdx.x;
    int t   = threadIdx.x;
    float x = in[row * 256 + t];
    float s = x, ss = x * x;
    #pragma unroll
    for (int o = 16; o; o >>= 1) {
        s  += __shfl_xor_sync(0xffffffffu, s,  o);
        ss += __shfl_xor_sync(0xffffffffu, ss, o);
    }
    __shared__ float ws[8], wss[8];
    int w = t >> 5, l = t & 31;
    if (l == 0) { ws[w] = s; wss[w] = ss; }
    __syncthreads();
    if (t == 0) {
        float a = 0.f, b = 0.f;
        #pragma unroll
        for (int i = 0; i < 8; i++) { a += ws[i]; b += wss[i]; }
        ws[0] = a; wss[0] = b;
    }
    __syncthreads();
    float mean = ws[0] * (1.f / 256.f);
    float var  = wss[0] * (1.f / 256.f) - mean * mean;
    out[row * 256 + t] = (x - mean) * rsqrtf(var + LN_EPS) * gam[t] + bet[t];
}

/* ------------------------------ tiled SGEMM ------------------------------- */
/* C[M,N] = act(A[M,K] @ B[N,K]^T + bias) + resid.  Row-major everywhere.     */
template<int BM, int BN, int BK, int TM, int TN>
__global__ __launch_bounds__(256)
void gemm_tn_k(const float* __restrict__ A, const float* __restrict__ Bw,
               float* __restrict__ C, int M, int N, int K,
               const float* __restrict__ bias, const float* __restrict__ resid,
               int act) {
    __shared__ float As[BK][BM + 1];
    __shared__ float Bs[BK][BN + 1];
    const int tid = threadIdx.x;
    const int bn0 = blockIdx.x * BN;
    const int bm0 = blockIdx.y * BM;
    const int tx = tid % (BN / TN);
    const int ty = tid / (BN / TN);

    float acc[TM][TN];
    #pragma unroll
    for (int i = 0; i < TM; i++)
        #pragma unroll
        for (int j = 0; j < TN; j++) acc[i][j] = 0.f;

    for (int k0 = 0; k0 < K; k0 += BK) {
        for (int i = tid; i < BM * BK; i += 256) {
            int m = i / BK, k = i % BK;
            As[k][m] = A[(size_t)(bm0 + m) * K + k0 + k];
        }
        for (int i = tid; i < BN * BK; i += 256) {
            int n = i / BK, k = i % BK;
            Bs[k][n] = Bw[(size_t)(bn0 + n) * K + k0 + k];
        }
        __syncthreads();
        #pragma unroll
        for (int kk = 0; kk < BK; kk++) {
            float ar[TM], br[TN];
            #pragma unroll
            for (int i = 0; i < TM; i++) ar[i] = As[kk][ty * TM + i];
            #pragma unroll
            for (int j = 0; j < TN; j++) br[j] = Bs[kk][tx * TN + j];
            #pragma unroll
            for (int i = 0; i < TM; i++)
                #pragma unroll
                for (int j = 0; j < TN; j++) acc[i][j] += ar[i] * br[j];
        }
        __syncthreads();
    }

    #pragma unroll
    for (int i = 0; i < TM; i++) {
        int m = bm0 + ty * TM + i;
        #pragma unroll
        for (int j = 0; j < TN; j++) {
            int n = bn0 + tx * TN + j;
            float v = acc[i][j];
            if (bias)  v += bias[n];
            if (act == 1) v = fmaxf(v, 0.f);
            if (resid) v += resid[(size_t)m * N + n];
            C[(size_t)m * N + n] = v;
        }
    }
}

/* --------------------------- attention kernel ----------------------------- */
/* grid (8 chunks of 128 j, 32 batches), 256 threads = 8 warps.
 * Each warp handles one token j at a time: dot q[i]·k[j] for all 8 slots,
 * softmax over slots, +eps, store attn, accumulate row sums.               */
__global__ void attn_k() {
    int b = blockIdx.y, chunk = blockIdx.x;
    __shared__ float qs[8][256];
    __shared__ float rs[8];
    int t = threadIdx.x;
    for (int idx = t; idx < NSLOT * 256; idx += 256)
        qs[idx >> 8][idx & 255] = g_q[b * NSLOT * 256 + idx];
    if (t < 8) rs[t] = 0.f;
    __syncthreads();

    int w = t >> 5, l = t & 31;
    const float* Kb = g_Km + (size_t)b * NTOK * 256;

    for (int jj = 0; jj < 16; jj++) {
        int j = chunk * 128 + w * 16 + jj;
        float acc[8] = {0.f, 0.f, 0.f, 0.f, 0.f, 0.f, 0.f, 0.f};
        #pragma unroll
        for (int kk = 0; kk < 8; kk++) {
            float kv = Kb[(size_t)j * 256 + kk * 32 + l];
            #pragma unroll
            for (int i = 0; i < 8; i++) acc[i] += kv * qs[i][kk * 32 + l];
        }
        #pragma unroll
        for (int i = 0; i < 8; i++)
            #pragma unroll
            for (int o = 16; o; o >>= 1)
                acc[i] += __shfl_xor_sync(0xffffffffu, acc[i], o);

        float m = -1e30f;
        #pragma unroll
        for (int i = 0; i < 8; i++) m = fmaxf(m, acc[i] * SCALE);
        float e[8], sum = 0.f;
        #pragma unroll
        for (int i = 0; i < 8; i++) { e[i] = expf(acc[i] * SCALE - m); sum += e[i]; }
        float inv = 1.f / sum;
        if (l < 8) {
            float a = 0.f;
            #pragma unroll
            for (int i = 0; i < 8; i++) a = (l == i) ? (e[i] * inv + ATTN_EPS) : a;
            g_attn[((size_t)b * NSLOT + l) * NTOK + j] = a;
            atomicAdd(&rs[l], a);
        }
    }
    __syncthreads();
    if (t < 8) atomicAdd(&g_rowsum[b * NSLOT + t], rs[t]);
}

/* updates[b,i,d] = sum_j attn[b,i,j]/rowsum[b,i] * v[b,j,d]
 * grid (4 d-chunks of 64, 32 batches), 256 threads = 4 j-groups × 64 d.     */
__global__ void updates_k() {
    int b = blockIdx.y, dch = blockIdx.x;
    __shared__ float as[8][NTOK];      // 32 KB
    __shared__ float invrs[8];
    __shared__ float red[4][8][64];    // 8 KB
    int t = threadIdx.x;
    if (t < 8) invrs[t] = 1.f / g_rowsum[b * NSLOT + t];
    __syncthreads();
    for (int idx = t; idx < 8 * NTOK; idx += 256) {
        int i = idx >> 10, j = idx & 1023;
        as[i][j] = g_attn[((size_t)b * NSLOT + i) * NTOK + j] * invrs[i];
    }
    __syncthreads();

    int jj = t >> 6, dc = t & 63;
    const float* Vb = g_Vm + (size_t)b * NTOK * 256 + dch * 64 + dc;
    float acc[8] = {0.f, 0.f, 0.f, 0.f, 0.f, 0.f, 0.f, 0.f};
    for (int j = jj; j < NTOK; j += 4) {
        float vv = Vb[(size_t)j * 256];
        #pragma unroll
        for (int i = 0; i < 8; i++) acc[i] += as[i][j] * vv;
    }
    #pragma unroll
    for (int i = 0; i < 8; i++) red[jj][i][dc] = acc[i];
    __syncthreads();
    if (jj == 0) {
        #pragma unroll
        for (int i = 0; i < 8; i++) {
            float s = red[0][i][dc] + red[1][i][dc] + red[2][i][dc] + red[3][i][dc];
            g_upd[((size_t)b * NSLOT + i) * 256 + dch * 64 + dc] = s;
        }
    }
}

/* GRU gate fusion, in-place on slots. */
__global__ void gru_gate_k() {
    int idx = blockIdx.x * 256 + threadIdx.x;   // 65536
    int r = idx >> 8, cc = idx & 255;
    const float* gi = g_gi + (size_t)r * 768;
    const float* gh = g_gh + (size_t)r * 768;
    float ir = gi[cc], iz = gi[256 + cc], in_ = gi[512 + cc];
    float hr = gh[cc], hz = gh[256 + cc], hn  = gh[512 + cc];
    float h  = g_slots[idx];
    float rg = 1.f / (1.f + expf(-(ir + hr)));
    float z  = 1.f / (1.f + expf(-(iz + hz)));
    float nn = tanhf(in_ + rg * hn);
    g_slots[idx] = (1.f - z) * nn + z * h;
}

/* ------------------------------- launcher --------------------------------- */
extern "C" void kernel_launch(void* const* d_in, const int* in_sizes, int n_in,
                              void* d_out, int out_size) {
    const float* inputs = (const float*)d_in[0];
    const float* noise  = (const float*)d_in[1];
    const float* mu     = (const float*)d_in[2];
    const float* lsig   = (const float*)d_in[3];
    const float* Wq     = (const float*)d_in[4];
    const float* Wk     = (const float*)d_in[5];
    const float* Wv     = (const float*)d_in[6];
    const float* wih    = (const float*)d_in[7];
    const float* whh    = (const float*)d_in[8];
    const float* bih    = (const float*)d_in[9];
    const float* bhh    = (const float*)d_in[10];
    const float* w1     = (const float*)d_in[11];
    const float* b1     = (const float*)d_in[12];
    const float* w2     = (const float*)d_in[13];
    const float* b2     = (const float*)d_in[14];
    const float* lin_g  = (const float*)d_in[15];
    const float* lin_b  = (const float*)d_in[16];
    const float* ls_g   = (const float*)d_in[17];
    const float* ls_b   = (const float*)d_in[18];
    const float* lf_g   = (const float*)d_in[19];
    const float* lf_b   = (const float*)d_in[20];

    float *pX, *pK, *pV, *pslots, *psnorm, *pq, *pupd, *pgi, *pgh, *pt1, *pt2;
    cudaGetSymbolAddress((void**)&pX,     g_X);
    cudaGetSymbolAddress((void**)&pK,     g_Km);
    cudaGetSymbolAddress((void**)&pV,     g_Vm);
    cudaGetSymbolAddress((void**)&pslots, g_slots);
    cudaGetSymbolAddress((void**)&psnorm, g_snorm);
    cudaGetSymbolAddress((void**)&pq,     g_q);
    cudaGetSymbolAddress((void**)&pupd,   g_upd);
    cudaGetSymbolAddress((void**)&pgi,    g_gi);
    cudaGetSymbolAddress((void**)&pgh,    g_gh);
    cudaGetSymbolAddress((void**)&pt1,    g_t1);
    cudaGetSymbolAddress((void**)&pt2,    g_t2);

    /* slots = mu + exp(log_sigma) * noise */
    slots_init_k<<<ROWS, 256>>>(mu, lsig, noise);

    /* x = LN(inputs); k = x@Wk^T; v = x@Wv^T */
    ln_rows_k<<<BATCH * NTOK, 256>>>(inputs, pX, lin_g, lin_b);
    gemm_tn_k<128,128,16,8,8><<<dim3(DDIM/128, BATCH*NTOK/128), 256>>>(
        pX, Wk, pK, BATCH*NTOK, DDIM, CDIM, nullptr, nullptr, 0);
    gemm_tn_k<128,128,16,8,8><<<dim3(DDIM/128, BATCH*NTOK/128), 256>>>(
        pX, Wv, pV, BATCH*NTOK, DDIM, CDIM, nullptr, nullptr, 0);

    for (int it = 0; it < NITER; it++) {
        /* s = LN(slots); q = s@Wq^T */
        ln_rows_k<<<ROWS, 256>>>(pslots, psnorm, ls_g, ls_b);
        gemm_tn_k<64,64,16,4,4><<<dim3(DDIM/64, ROWS/64), 256>>>(
            psnorm, Wq, pq, ROWS, DDIM, DDIM, nullptr, nullptr, 0);

        /* attention */
        zero_rowsum_k<<<1, ROWS>>>();
        attn_k<<<dim3(NTOK/128, BATCH), 256>>>();
        updates_k<<<dim3(4, BATCH), 256>>>();

        /* GRU */
        gemm_tn_k<64,64,16,4,4><<<dim3(768/64, ROWS/64), 256>>>(
            pupd, wih, pgi, ROWS, 768, DDIM, bih, nullptr, 0);
        gemm_tn_k<64,64,16,4,4><<<dim3(768/64, ROWS/64), 256>>>(
            pslots, whh, pgh, ROWS, 768, DDIM, bhh, nullptr, 0);
        gru_gate_k<<<ROWS, 256>>>();

        /* MLP with residual */
        ln_rows_k<<<ROWS, 256>>>(pslots, pt1, lf_g, lf_b);
        gemm_tn_k<64,64,16,4,4><<<dim3(1024/64, ROWS/64), 256>>>(
            pt1, w1, pt2, ROWS, 1024, DDIM, b1, nullptr, 1);
        gemm_tn_k<64,64,16,4,4><<<dim3(DDIM/64, ROWS/64), 256>>>(
            pt2, w2, pslots, ROWS, DDIM, 1024, b2, pslots, 0);
    }

    copy_out_k<<<ROWS, 256>>>((float*)d_out);
}

// round 3
// speedup vs baseline: 2.5115x; 2.5115x over previous
#include <cuda_runtime.h>
#include <math.h>

#define BATCH 32
#define NTOK  1024
#define CDIM  256
#define DDIM  256
#define NSLOT 8
#define ROWS  (BATCH*NSLOT)   /* 256 */
#define NITER 3
#define NCHUNK 8              /* token chunks of 128 */
#define ATTN_EPS 1e-8f
#define LN_EPS   1e-5f
#define SCALE    0.0625f      /* 256^-0.5 */

/* ------------------------ scratch (device globals) ------------------------ */
__device__ float g_mean[BATCH*NTOK];
__device__ float g_rstd[BATCH*NTOK];
__device__ float g_Km  [BATCH*NTOK*DDIM];   // keys
__device__ float g_Vm  [BATCH*NTOK*DDIM];   // values
__device__ float g_slots[ROWS*DDIM];
__device__ float g_snorm[ROWS*DDIM];
__device__ float g_q    [ROWS*DDIM];
__device__ float g_updp [NCHUNK*BATCH*9*DDIM];  // partial U (8 slots) + Vsum (row 8)
__device__ float g_rp   [NCHUNK*BATCH*NSLOT];   // partial slot rowsums
__device__ float g_upd  [ROWS*DDIM];
__device__ float g_gi   [ROWS*3*DDIM];
__device__ float g_gh   [ROWS*3*DDIM];
__device__ float g_t1   [ROWS*DDIM];
__device__ float g_t2   [ROWS*4*DDIM];

/* ------------------------------ small kernels ----------------------------- */
__global__ void slots_init_k(const float* __restrict__ mu,
                             const float* __restrict__ ls,
                             const float* __restrict__ noise) {
    int idx = blockIdx.x * 256 + threadIdx.x;      // 65536 total
    int dcol = idx & 255;
    g_slots[idx] = mu[dcol] + expf(ls[dcol]) * noise[idx];
}

__global__ void copy_out_k(float* __restrict__ out) {
    int idx = blockIdx.x * 256 + threadIdx.x;
    out[idx] = g_slots[idx];
}

/* Per-row LN stats for the big input: one warp per row. */
__global__ void ln_stats_k(const float* __restrict__ in) {
    int row = blockIdx.x * 8 + (threadIdx.x >> 5);
    int l = threadIdx.x & 31;
    const float* p = in + (size_t)row * 256;
    float s = 0.f, ss = 0.f;
    #pragma unroll
    for (int i = 0; i < 8; i++) { float x = p[i * 32 + l]; s += x; ss += x * x; }
    #pragma unroll
    for (int o = 16; o; o >>= 1) {
        s  += __shfl_xor_sync(0xffffffffu, s,  o);
        ss += __shfl_xor_sync(0xffffffffu, ss, o);
    }
    if (l == 0) {
        float m = s * (1.f / 256.f);
        float v = ss * (1.f / 256.f) - m * m;
        g_mean[row] = m;
        g_rstd[row] = rsqrtf(v + LN_EPS);
    }
}

/* LayerNorm over last dim (=256), small row counts. One block per row. */
__global__ void ln_rows_k(const float* __restrict__ in, float* __restrict__ out,
                          const float* __restrict__ gam, const float* __restrict__ bet) {
    int row = blockIdx.x;
    int t   = threadIdx.x;
    float x = in[row * 256 + t];
    float s = x, ss = x * x;
    #pragma unroll
    for (int o = 16; o; o >>= 1) {
        s  += __shfl_xor_sync(0xffffffffu, s,  o);
        ss += __shfl_xor_sync(0xffffffffu, ss, o);
    }
    __shared__ float ws[8], wss[8];
    int w = t >> 5, l = t & 31;
    if (l == 0) { ws[w] = s; wss[w] = ss; }
    __syncthreads();
    if (t == 0) {
        float a = 0.f, b = 0.f;
        #pragma unroll
        for (int i = 0; i < 8; i++) { a += ws[i]; b += wss[i]; }
        ws[0] = a; wss[0] = b;
    }
    __syncthreads();
    float mean = ws[0] * (1.f / 256.f);
    float var  = wss[0] * (1.f / 256.f) - mean * mean;
    out[row * 256 + t] = (x - mean) * rsqrtf(var + LN_EPS) * gam[t] + bet[t];
}

/* ------------------ fused LN + K/V GEMM (128x128x8, dbuf) ----------------- */
/* C = LN(X) @ W^T, W selected by blockIdx.x: {0,1}->Wk->g_Km, {2,3}->Wv->g_Vm */
__global__ __launch_bounds__(256)
void kv_gemm_k(const float* __restrict__ X,
               const float* __restrict__ Wk, const float* __restrict__ Wv,
               const float* __restrict__ lng, const float* __restrict__ lnb) {
    __shared__ float As[2][8][128];
    __shared__ float Bs[2][8][128];
    __shared__ float gsm[256], bsm[256];
    const int tid = threadIdx.x;
    const int bx = blockIdx.x, by = blockIdx.y;
    const float* Bw = (bx < 2) ? Wk : Wv;
    float* C = (bx < 2) ? g_Km : g_Vm;
    const int n0 = (bx & 1) * 128, m0 = by * 128;

    gsm[tid] = lng[tid];
    bsm[tid] = lnb[tid];

    const int lrow = tid >> 1, lcol = (tid & 1) * 4;
    const int tx = tid & 15, ty = tid >> 4;
    const float mean_a = g_mean[m0 + lrow];
    const float rstd_a = g_rstd[m0 + lrow];
    const float* Arow = X  + (size_t)(m0 + lrow) * 256;
    const float* Brow = Bw + (size_t)(n0 + lrow) * 256;

    __syncthreads();   /* gsm/bsm ready */

    /* stage 0 */
    {
        float4 av = *(const float4*)(Arow + lcol);
        float4 bv = *(const float4*)(Brow + lcol);
        As[0][lcol + 0][lrow] = (av.x - mean_a) * rstd_a * gsm[lcol + 0] + bsm[lcol + 0];
        As[0][lcol + 1][lrow] = (av.y - mean_a) * rstd_a * gsm[lcol + 1] + bsm[lcol + 1];
        As[0][lcol + 2][lrow] = (av.z - mean_a) * rstd_a * gsm[lcol + 2] + bsm[lcol + 2];
        As[0][lcol + 3][lrow] = (av.w - mean_a) * rstd_a * gsm[lcol + 3] + bsm[lcol + 3];
        Bs[0][lcol + 0][lrow] = bv.x;
        Bs[0][lcol + 1][lrow] = bv.y;
        Bs[0][lcol + 2][lrow] = bv.z;
        Bs[0][lcol + 3][lrow] = bv.w;
    }
    __syncthreads();

    float acc[8][8];
    #pragma unroll
    for (int i = 0; i < 8; i++)
        #pragma unroll
        for (int j = 0; j < 8; j++) acc[i][j] = 0.f;

    int buf = 0;
    for (int k0 = 0; k0 < 256; k0 += 8) {
        const bool nxt = (k0 + 8 < 256);
        float4 anx, bnx;
        if (nxt) {
            anx = *(const float4*)(Arow + k0 + 8 + lcol);
            bnx = *(const float4*)(Brow + k0 + 8 + lcol);
        }
        #pragma unroll
        for (int kk = 0; kk < 8; kk++) {
            float a[8], b[8];
            *(float4*)&a[0] = *(const float4*)&As[buf][kk][ty * 8];
            *(float4*)&a[4] = *(const float4*)&As[buf][kk][ty * 8 + 4];
            *(float4*)&b[0] = *(const float4*)&Bs[buf][kk][tx * 8];
            *(float4*)&b[4] = *(const float4*)&Bs[buf][kk][tx * 8 + 4];
            #pragma unroll
            for (int i = 0; i < 8; i++)
                #pragma unroll
                for (int j = 0; j < 8; j++) acc[i][j] += a[i] * b[j];
        }
        if (nxt) {
            const int kg = k0 + 8 + lcol;
            As[buf ^ 1][lcol + 0][lrow] = (anx.x - mean_a) * rstd_a * gsm[kg + 0] + bsm[kg + 0];
            As[buf ^ 1][lcol + 1][lrow] = (anx.y - mean_a) * rstd_a * gsm[kg + 1] + bsm[kg + 1];
            As[buf ^ 1][lcol + 2][lrow] = (anx.z - mean_a) * rstd_a * gsm[kg + 2] + bsm[kg + 2];
            As[buf ^ 1][lcol + 3][lrow] = (anx.w - mean_a) * rstd_a * gsm[kg + 3] + bsm[kg + 3];
            Bs[buf ^ 1][lcol + 0][lrow] = bnx.x;
            Bs[buf ^ 1][lcol + 1][lrow] = bnx.y;
            Bs[buf ^ 1][lcol + 2][lrow] = bnx.z;
            Bs[buf ^ 1][lcol + 3][lrow] = bnx.w;
            __syncthreads();
            buf ^= 1;
        }
    }

    #pragma unroll
    for (int i = 0; i < 8; i++) {
        int m = m0 + ty * 8 + i;
        float4 v0 = make_float4(acc[i][0], acc[i][1], acc[i][2], acc[i][3]);
        float4 v1 = make_float4(acc[i][4], acc[i][5], acc[i][6], acc[i][7]);
        *(float4*)&C[(size_t)m * 256 + n0 + tx * 8]     = v0;
        *(float4*)&C[(size_t)m * 256 + n0 + tx * 8 + 4] = v1;
    }
}

/* ------------------------- small GEMM (64x64x32) -------------------------- */
/* C[M=256,N] = act(A @ Bw^T + bias) + resid */
template<int ACT>
__global__ __launch_bounds__(256)
void gemm_s_k(const float* __restrict__ A, const float* __restrict__ Bw,
              float* __restrict__ C, int N, int K,
              const float* __restrict__ bias, const float* __restrict__ resid) {
    __shared__ float As[32][64];
    __shared__ float Bs[32][64];
    const int tid = threadIdx.x;
    const int n0 = blockIdx.x * 64, m0 = blockIdx.y * 64;
    const int lrow = tid >> 2, lcol = (tid & 3) * 8;
    const int tx = tid & 15, ty = tid >> 4;

    float acc[4][4];
    #pragma unroll
    for (int i = 0; i < 4; i++)
        #pragma unroll
        for (int j = 0; j < 4; j++) acc[i][j] = 0.f;

    const float* Ar = A  + (size_t)(m0 + lrow) * K;
    const float* Br = Bw + (size_t)(n0 + lrow) * K;

    for (int k0 = 0; k0 < K; k0 += 32) {
        float4 a0 = *(const float4*)(Ar + k0 + lcol);
        float4 a1 = *(const float4*)(Ar + k0 + lcol + 4);
        float4 b0 = *(const float4*)(Br + k0 + lcol);
        float4 b1 = *(const float4*)(Br + k0 + lcol + 4);
        __syncthreads();
        As[lcol + 0][lrow] = a0.x; As[lcol + 1][lrow] = a0.y;
        As[lcol + 2][lrow] = a0.z; As[lcol + 3][lrow] = a0.w;
        As[lcol + 4][lrow] = a1.x; As[lcol + 5][lrow] = a1.y;
        As[lcol + 6][lrow] = a1.z; As[lcol + 7][lrow] = a1.w;
        Bs[lcol + 0][lrow] = b0.x; Bs[lcol + 1][lrow] = b0.y;
        Bs[lcol + 2][lrow] = b0.z; Bs[lcol + 3][lrow] = b0.w;
        Bs[lcol + 4][lrow] = b1.x; Bs[lcol + 5][lrow] = b1.y;
        Bs[lcol + 6][lrow] = b1.z; Bs[lcol + 7][lrow] = b1.w;
        __syncthreads();
        #pragma unroll
        for (int kk = 0; kk < 32; kk++) {
            float a[4], b[4];
            *(float4*)&a[0] = *(const float4*)&As[kk][ty * 4];
            *(float4*)&b[0] = *(const float4*)&Bs[kk][tx * 4];
            #pragma unroll
            for (int i = 0; i < 4; i++)
                #pragma unroll
                for (int j = 0; j < 4; j++) acc[i][j] += a[i] * b[j];
        }
    }

    #pragma unroll
    for (int i = 0; i < 4; i++) {
        int m = m0 + ty * 4 + i;
        #pragma unroll
        for (int j = 0; j < 4; j++) {
            int n = n0 + tx * 4 + j;
            float v = acc[i][j];
            if (bias)  v += bias[n];
            if (ACT == 1) v = fmaxf(v, 0.f);
            if (resid) v += resid[(size_t)m * N + n];
            C[(size_t)m * N + n] = v;
        }
    }
}

/* --------------------- fused attention (dots+softmax+pV) ------------------ */
/* grid (NCHUNK=8, BATCH=32), 256 threads. Per chunk of 128 tokens:
 * phase A: per-warp dots q_i.k_j, softmax over 8 slots, p stored to smem,
 *          slot rowsum partials accumulated.
 * phase B: per-thread d-column: U_i += p_ij * v_jd over chunk; plus Vsum.   */
__global__ void attn_fused_k() {
    int b = blockIdx.y, ch = blockIdx.x;
    __shared__ float qs[8][256];     // 8 KB
    __shared__ float ps[128][8];     // 4 KB  p for this chunk, [j_local][slot]
    __shared__ float rpart[8];
    int t = threadIdx.x;
    for (int idx = t; idx < NSLOT * 256; idx += 256)
        qs[idx >> 8][idx & 255] = g_q[b * NSLOT * 256 + idx];
    if (t < 8) rpart[t] = 0.f;
    __syncthreads();

    int w = t >> 5, l = t & 31;
    const float* Kb = g_Km + ((size_t)b * NTOK + ch * 128) * 256;

    float racc = 0.f;
    for (int jj = 0; jj < 16; jj++) {
        int j = w * 16 + jj;
        float acc[8] = {0.f, 0.f, 0.f, 0.f, 0.f, 0.f, 0.f, 0.f};
        #pragma unroll
        for (int kk = 0; kk < 8; kk++) {
            float kv = Kb[(size_t)j * 256 + kk * 32 + l];
            #pragma unroll
            for (int i = 0; i < 8; i++) acc[i] += kv * qs[i][kk * 32 + l];
        }
        #pragma unroll
        for (int i = 0; i < 8; i++)
            #pragma unroll
            for (int o = 16; o; o >>= 1)
                acc[i] += __shfl_xor_sync(0xffffffffu, acc[i], o);

        float m = -1e30f;
        #pragma unroll
        for (int i = 0; i < 8; i++) m = fmaxf(m, acc[i] * SCALE);
        float e[8], sum = 0.f;
        #pragma unroll
        for (int i = 0; i < 8; i++) { e[i] = expf(acc[i] * SCALE - m); sum += e[i]; }
        float inv = 1.f / sum;
        if (l < 8) {
            float pv = 0.f;
            #pragma unroll
            for (int i = 0; i < 8; i++) pv = (l == i) ? (e[i] * inv) : pv;
            ps[j][l] = pv;
            racc += pv;
        }
    }
    if (l < 8) atomicAdd(&rpart[l], racc);
    __syncthreads();

    /* phase B: thread t owns column d = t */
    const float* Vb = g_Vm + ((size_t)b * NTOK + ch * 128) * 256;
    float u[8] = {0.f, 0.f, 0.f, 0.f, 0.f, 0.f, 0.f, 0.f};
    float vs = 0.f;
    for (int j = 0; j < 128; j++) {
        float vv = Vb[(size_t)j * 256 + t];
        vs += vv;
        #pragma unroll
        for (int i = 0; i < 8; i++) u[i] += ps[j][i] * vv;
    }
    float* up = g_updp + ((size_t)ch * BATCH + b) * 9 * 256;
    #pragma unroll
    for (int i = 0; i < 8; i++) up[i * 256 + t] = u[i];
    up[8 * 256 + t] = vs;
    if (t < 8) g_rp[((size_t)ch * BATCH + b) * 8 + t] = rpart[t];
}

/* updates = (sum_ch U + eps*Vsum) / (sum_ch r + 1024*eps) */
__global__ void attn_reduce_k() {
    int idx = blockIdx.x * 256 + threadIdx.x;   // 65536: [b][i][d]
    int b = idx >> 11, i = (idx >> 8) & 7, d = idx & 255;
    float s = 0.f, vs = 0.f, r = 0.f;
    #pragma unroll
    for (int ch = 0; ch < NCHUNK; ch++) {
        const float* up = g_updp + ((size_t)ch * BATCH + b) * 9 * 256;
        s  += up[i * 256 + d];
        vs += up[8 * 256 + d];
        r  += g_rp[((size_t)ch * BATCH + b) * 8 + i];
    }
    g_upd[((size_t)b * NSLOT + i) * 256 + d] =
        (s + ATTN_EPS * vs) / (r + (float)NTOK * ATTN_EPS);
}

/* GRU gate fusion, in-place on slots. */
__global__ void gru_gate_k() {
    int idx = blockIdx.x * 256 + threadIdx.x;   // 65536
    int r = idx >> 8, cc = idx & 255;
    const float* gi = g_gi + (size_t)r * 768;
    const float* gh = g_gh + (size_t)r * 768;
    float ir = gi[cc], iz = gi[256 + cc], in_ = gi[512 + cc];
    float hr = gh[cc], hz = gh[256 + cc], hn  = gh[512 + cc];
    float h  = g_slots[idx];
    float rg = 1.f / (1.f + expf(-(ir + hr)));
    float z  = 1.f / (1.f + expf(-(iz + hz)));
    float nn = tanhf(in_ + rg * hn);
    g_slots[idx] = (1.f - z) * nn + z * h;
}

/* ------------------------------- launcher --------------------------------- */
extern "C" void kernel_launch(void* const* d_in, const int* in_sizes, int n_in,
                              void* d_out, int out_size) {
    const float* inputs = (const float*)d_in[0];
    const float* noise  = (const float*)d_in[1];
    const float* mu     = (const float*)d_in[2];
    const float* lsig   = (const float*)d_in[3];
    const float* Wq     = (const float*)d_in[4];
    const float* Wk     = (const float*)d_in[5];
    const float* Wv     = (const float*)d_in[6];
    const float* wih    = (const float*)d_in[7];
    const float* whh    = (const float*)d_in[8];
    const float* bih    = (const float*)d_in[9];
    const float* bhh    = (const float*)d_in[10];
    const float* w1     = (const float*)d_in[11];
    const float* b1     = (const float*)d_in[12];
    const float* w2     = (const float*)d_in[13];
    const float* b2     = (const float*)d_in[14];
    const float* lin_g  = (const float*)d_in[15];
    const float* lin_b  = (const float*)d_in[16];
    const float* ls_g   = (const float*)d_in[17];
    const float* ls_b   = (const float*)d_in[18];
    const float* lf_g   = (const float*)d_in[19];
    const float* lf_b   = (const float*)d_in[20];

    float *pslots, *psnorm, *pq, *pupd, *pgi, *pgh, *pt1, *pt2;
    cudaGetSymbolAddress((void**)&pslots, g_slots);
    cudaGetSymbolAddress((void**)&psnorm, g_snorm);
    cudaGetSymbolAddress((void**)&pq,     g_q);
    cudaGetSymbolAddress((void**)&pupd,   g_upd);
    cudaGetSymbolAddress((void**)&pgi,    g_gi);
    cudaGetSymbolAddress((void**)&pgh,    g_gh);
    cudaGetSymbolAddress((void**)&pt1,    g_t1);
    cudaGetSymbolAddress((void**)&pt2,    g_t2);

    /* slots = mu + exp(log_sigma) * noise */
    slots_init_k<<<ROWS, 256>>>(mu, lsig, noise);

    /* LN stats + fused LN->K/V GEMM */
    ln_stats_k<<<BATCH * NTOK / 8, 256>>>(inputs);
    kv_gemm_k<<<dim3(4, BATCH * NTOK / 128), 256>>>(inputs, Wk, Wv, lin_g, lin_b);

    for (int it = 0; it < NITER; it++) {
        ln_rows_k<<<ROWS, 256>>>(pslots, psnorm, ls_g, ls_b);
        gemm_s_k<0><<<dim3(4, 4), 256>>>(psnorm, Wq, pq, 256, 256, nullptr, nullptr);

        attn_fused_k<<<dim3(NCHUNK, BATCH), 256>>>();
        attn_reduce_k<<<256, 256>>>();

        gemm_s_k<0><<<dim3(12, 4), 256>>>(pupd,   wih, pgi, 768, 256, bih, nullptr);
        gemm_s_k<0><<<dim3(12, 4), 256>>>(pslots, whh, pgh, 768, 256, bhh, nullptr);
        gru_gate_k<<<ROWS, 256>>>();

        ln_rows_k<<<ROWS, 256>>>(pslots, pt1, lf_g, lf_b);
        gemm_s_k<1><<<dim3(16, 4), 256>>>(pt1, w1, pt2, 1024, 256, b1, nullptr);
        gemm_s_k<0><<<dim3(4, 4), 256>>>(pt2, w2, pslots, 256, 1024, b2, pslots);
    }

    copy_out_k<<<ROWS, 256>>>((float*)d_out);
}

// round 8
// speedup vs baseline: 2.8889x; 1.1502x over previous
#include <cuda_runtime.h>
#include <cuda_bf16.h>
#include <math.h>
#include <stdint.h>

#define BATCH 32
#define NTOK  1024
#define CDIM  256
#define DDIM  256
#define NSLOT 8
#define ROWS  (BATCH*NSLOT)   /* 256 */
#define NITER 3
#define NCHUNK 8              /* token chunks of 128 for attention */
#define ATTN_EPS 1e-8f
#define LN_EPS   1e-5f
#define SCALE    0.0625f      /* 256^-0.5 */

/* ------------------------ scratch (device globals) ------------------------ */
__device__ __align__(256) __nv_bfloat16 g_a_hi[BATCH*NTOK*CDIM];   // LN(x) hi
__device__ __align__(256) __nv_bfloat16 g_a_lo[BATCH*NTOK*CDIM];   // LN(x) lo
__device__ __align__(256) __nv_bfloat16 g_w_hi[2*DDIM*CDIM];       // [Wk;Wv] hi
__device__ __align__(256) __nv_bfloat16 g_w_lo[2*DDIM*CDIM];       // [Wk;Wv] lo
__device__ __align__(256) float g_Km  [BATCH*NTOK*DDIM];   // keys (fp32)
__device__ __align__(256) float g_Vm  [BATCH*NTOK*DDIM];   // values (fp32)
__device__ __align__(256) float g_slots[ROWS*DDIM];
__device__ __align__(256) float g_snorm[ROWS*DDIM];
__device__ __align__(256) float g_q    [ROWS*DDIM];
__device__ __align__(256) float g_updp [NCHUNK*BATCH*9*DDIM];  // partials + Vsum
__device__ __align__(256) float g_rp   [NCHUNK*BATCH*NSLOT];   // partial rowsums
__device__ __align__(256) float g_upd  [ROWS*DDIM];
__device__ __align__(256) float g_gi   [ROWS*3*DDIM];
__device__ __align__(256) float g_gh   [ROWS*3*DDIM];
__device__ __align__(256) float g_t1   [ROWS*DDIM];
__device__ __align__(256) float g_t2   [ROWS*4*DDIM];

/* ------------------------------ small kernels ----------------------------- */
__global__ void slots_init_k(const float* __restrict__ mu,
                             const float* __restrict__ ls,
                             const float* __restrict__ noise) {
    int idx = blockIdx.x * 256 + threadIdx.x;      // 65536 total
    int dcol = idx & 255;
    g_slots[idx] = mu[dcol] + expf(ls[dcol]) * noise[idx];
}

__global__ void copy_out_k(float* __restrict__ out) {
    int idx = blockIdx.x * 256 + threadIdx.x;
    out[idx] = g_slots[idx];
}

/* LN(x) -> split bf16 hi/lo. One block per row. */
__global__ void prep_a_k(const float* __restrict__ in,
                         const float* __restrict__ gam, const float* __restrict__ bet) {
    int row = blockIdx.x;
    int t   = threadIdx.x;
    float x = in[(size_t)row * 256 + t];
    float s = x, ss = x * x;
    #pragma unroll
    for (int o = 16; o; o >>= 1) {
        s  += __shfl_xor_sync(0xffffffffu, s,  o);
        ss += __shfl_xor_sync(0xffffffffu, ss, o);
    }
    __shared__ float ws[8], wss[8];
    int w = t >> 5, l = t & 31;
    if (l == 0) { ws[w] = s; wss[w] = ss; }
    __syncthreads();
    if (t == 0) {
        float a = 0.f, b = 0.f;
        #pragma unroll
        for (int i = 0; i < 8; i++) { a += ws[i]; b += wss[i]; }
        ws[0] = a; wss[0] = b;
    }
    __syncthreads();
    float mean = ws[0] * (1.f / 256.f);
    float var  = wss[0] * (1.f / 256.f) - mean * mean;
    float y = (x - mean) * rsqrtf(var + LN_EPS) * gam[t] + bet[t];
    __nv_bfloat16 hi = __float2bfloat16(y);
    __nv_bfloat16 lo = __float2bfloat16(y - __bfloat162float(hi));
    g_a_hi[(size_t)row * 256 + t] = hi;
    g_a_lo[(size_t)row * 256 + t] = lo;
}

/* Wk/Wv -> split bf16 hi/lo. blockIdx.x = 0..511 rows (Wk rows then Wv rows). */
__global__ void prep_w_k(const float* __restrict__ Wk, const float* __restrict__ Wv) {
    int row = blockIdx.x;
    int t = threadIdx.x;
    const float* src = (row < 256) ? Wk : Wv;
    int n = row & 255;
    float y = src[(size_t)n * 256 + t];
    __nv_bfloat16 hi = __float2bfloat16(y);
    __nv_bfloat16 lo = __float2bfloat16(y - __bfloat162float(hi));
    g_w_hi[(size_t)row * 256 + t] = hi;
    g_w_lo[(size_t)row * 256 + t] = lo;
}

/* LayerNorm over last dim (=256), small row counts. One block per row. */
__global__ void ln_rows_k(const float* __restrict__ in, float* __restrict__ out,
                          const float* __restrict__ gam, const float* __restrict__ bet) {
    int row = blockIdx.x;
    int t   = threadIdx.x;
    float x = in[row * 256 + t];
    float s = x, ss = x * x;
    #pragma unroll
    for (int o = 16; o; o >>= 1) {
        s  += __shfl_xor_sync(0xffffffffu, s,  o);
        ss += __shfl_xor_sync(0xffffffffu, ss, o);
    }
    __shared__ float ws[8], wss[8];
    int w = t >> 5, l = t & 31;
    if (l == 0) { ws[w] = s; wss[w] = ss; }
    __syncthreads();
    if (t == 0) {
        float a = 0.f, b = 0.f;
        #pragma unroll
        for (int i = 0; i < 8; i++) { a += ws[i]; b += wss[i]; }
        ws[0] = a; wss[0] = b;
    }
    __syncthreads();
    float mean = ws[0] * (1.f / 256.f);
    float var  = wss[0] * (1.f / 256.f) - mean * mean;
    out[row * 256 + t] = (x - mean) * rsqrtf(var + LN_EPS) * gam[t] + bet[t];
}

/* -------------- K/V GEMM via mma.sync bf16 (split hi/lo, 3-term) ---------- */
/* Grid (4, 256): bx -> {mat = bx>>1 (0=K,1=V), n0 = (bx&1)*128}; by -> m0.   */
/* CTA 128x128, 8 warps (4 M x 2 N), warp tile 32x64.                         */
/* K=256 in 4 chunks of 64; smem row stride 36 u32 (conflict-free frags).     */
#define KV_STRIDE_U 36
#define KV_TILE_U   (128*KV_STRIDE_U)     /* 4608 u32 = 18432 B */
#define KV_SMEM_SZ  (4*KV_TILE_U*4)       /* 73728 B */

#define MMA_BF16(c, a, b0v, b1v) \
    asm volatile("mma.sync.aligned.m16n8k16.row.col.f32.bf16.bf16.f32 " \
        "{%0,%1,%2,%3}, {%4,%5,%6,%7}, {%8,%9}, {%0,%1,%2,%3};" \
        : "+f"((c)[0]), "+f"((c)[1]), "+f"((c)[2]), "+f"((c)[3]) \
        : "r"((a)[0]), "r"((a)[1]), "r"((a)[2]), "r"((a)[3]), \
          "r"(b0v), "r"(b1v))

/* load 128x64 bf16 tile (global row stride 256) into smem, stride 36 u32 */
__device__ __forceinline__ void kv_ldtile(const __nv_bfloat16* __restrict__ g,
                                          uint32_t* __restrict__ s, int t) {
    int row = t >> 1, h = t & 1;
    const uint4* src = (const uint4*)(g + (size_t)row * 256 + h * 32);
    uint4* dst = (uint4*)(s + row * KV_STRIDE_U + h * 16);
    #pragma unroll
    for (int i = 0; i < 4; i++) dst[i] = src[i];
}

__global__ __launch_bounds__(256)
void kv_mma_k() {
    extern __shared__ __align__(16) uint32_t us[];
    uint32_t* uAh = us;
    uint32_t* uAl = us + KV_TILE_U;
    uint32_t* uBh = us + 2 * KV_TILE_U;
    uint32_t* uBl = us + 3 * KV_TILE_U;

    int t = threadIdx.x, lane = t & 31, wid = t >> 5;
    int wm = wid & 3, wn = wid >> 2;        /* 4 x 2 warp grid */
    int mat = blockIdx.x >> 1;
    int n0  = (blockIdx.x & 1) * 128;
    int m0  = blockIdx.y * 128;

    const __nv_bfloat16* Ah = g_a_hi + (size_t)m0 * 256;
    const __nv_bfloat16* Al = g_a_lo + (size_t)m0 * 256;
    const __nv_bfloat16* Bh = g_w_hi + (size_t)(mat * 256 + n0) * 256;
    const __nv_bfloat16* Bl = g_w_lo + (size_t)(mat * 256 + n0) * 256;

    float acc[2][8][4];
    #pragma unroll
    for (int i = 0; i < 2; i++)
        #pragma unroll
        for (int j = 0; j < 8; j++)
            #pragma unroll
            for (int k = 0; k < 4; k++) acc[i][j][k] = 0.f;

    for (int c = 0; c < 4; c++) {
        __syncthreads();
        kv_ldtile(Ah + c * 64, uAh, t);
        kv_ldtile(Al + c * 64, uAl, t);
        kv_ldtile(Bh + c * 64, uBh, t);
        kv_ldtile(Bl + c * 64, uBl, t);
        __syncthreads();

        #pragma unroll
        for (int ks = 0; ks < 4; ks++) {
            int cu = ks * 8 + (lane & 3);           /* u32 col in tile */
            uint32_t ah[2][4], al[2][4];
            #pragma unroll
            for (int mt = 0; mt < 2; mt++) {
                int r = wm * 32 + mt * 16 + (lane >> 2);
                ah[mt][0] = uAh[r * KV_STRIDE_U + cu];
                ah[mt][1] = uAh[(r + 8) * KV_STRIDE_U + cu];
                ah[mt][2] = uAh[r * KV_STRIDE_U + cu + 4];
                ah[mt][3] = uAh[(r + 8) * KV_STRIDE_U + cu + 4];
                al[mt][0] = uAl[r * KV_STRIDE_U + cu];
                al[mt][1] = uAl[(r + 8) * KV_STRIDE_U + cu];
                al[mt][2] = uAl[r * KV_STRIDE_U + cu + 4];
                al[mt][3] = uAl[(r + 8) * KV_STRIDE_U + cu + 4];
            }
            #pragma unroll
            for (int nt = 0; nt < 8; nt++) {
                int rb = wn * 64 + nt * 8 + (lane >> 2);
                uint32_t bh0 = uBh[rb * KV_STRIDE_U + cu];
                uint32_t bh1 = uBh[rb * KV_STRIDE_U + cu + 4];
                uint32_t bl0 = uBl[rb * KV_STRIDE_U + cu];
                uint32_t bl1 = uBl[rb * KV_STRIDE_U + cu + 4];
                #pragma unroll
                for (int mt = 0; mt < 2; mt++) {
                    MMA_BF16(acc[mt][nt], ah[mt], bh0, bh1);
                    MMA_BF16(acc[mt][nt], al[mt], bh0, bh1);
                    MMA_BF16(acc[mt][nt], ah[mt], bl0, bl1);
                }
            }
        }
    }

    float* C = (mat == 0) ? g_Km : g_Vm;
    #pragma unroll
    for (int mt = 0; mt < 2; mt++) {
        #pragma unroll
        for (int nt = 0; nt < 8; nt++) {
            int row = m0 + wm * 32 + mt * 16 + (lane >> 2);
            int col = n0 + wn * 64 + nt * 8 + (lane & 3) * 2;
            float2 v0 = make_float2(acc[mt][nt][0], acc[mt][nt][1]);
            float2 v1 = make_float2(acc[mt][nt][2], acc[mt][nt][3]);
            *(float2*)&C[(size_t)row * 256 + col]       = v0;
            *(float2*)&C[(size_t)(row + 8) * 256 + col] = v1;
        }
    }
}

/* ------------------------- small GEMM (64x64x32) -------------------------- */
/* C[M=256,N] = act(A @ Bw^T + bias) + resid */
template<int ACT>
__global__ __launch_bounds__(256)
void gemm_s_k(const float* __restrict__ A, const float* __restrict__ Bw,
              float* __restrict__ C, int N, int K,
              const float* __restrict__ bias, const float* __restrict__ resid) {
    __shared__ float As[32][64];
    __shared__ float Bs[32][64];
    const int tid = threadIdx.x;
    const int n0 = blockIdx.x * 64, m0 = blockIdx.y * 64;
    const int lrow = tid >> 2, lcol = (tid & 3) * 8;
    const int tx = tid & 15, ty = tid >> 4;

    float acc[4][4];
    #pragma unroll
    for (int i = 0; i < 4; i++)
        #pragma unroll
        for (int j = 0; j < 4; j++) acc[i][j] = 0.f;

    const float* Ar = A  + (size_t)(m0 + lrow) * K;
    const float* Br = Bw + (size_t)(n0 + lrow) * K;

    for (int k0 = 0; k0 < K; k0 += 32) {
        float4 a0 = *(const float4*)(Ar + k0 + lcol);
        float4 a1 = *(const float4*)(Ar + k0 + lcol + 4);
        float4 b0 = *(const float4*)(Br + k0 + lcol);
        float4 b1 = *(const float4*)(Br + k0 + lcol + 4);
        __syncthreads();
        As[lcol + 0][lrow] = a0.x; As[lcol + 1][lrow] = a0.y;
        As[lcol + 2][lrow] = a0.z; As[lcol + 3][lrow] = a0.w;
        As[lcol + 4][lrow] = a1.x; As[lcol + 5][lrow] = a1.y;
        As[lcol + 6][lrow] = a1.z; As[lcol + 7][lrow] = a1.w;
        Bs[lcol + 0][lrow] = b0.x; Bs[lcol + 1][lrow] = b0.y;
        Bs[lcol + 2][lrow] = b0.z; Bs[lcol + 3][lrow] = b0.w;
        Bs[lcol + 4][lrow] = b1.x; Bs[lcol + 5][lrow] = b1.y;
        Bs[lcol + 6][lrow] = b1.z; Bs[lcol + 7][lrow] = b1.w;
        __syncthreads();
        #pragma unroll
        for (int kk = 0; kk < 32; kk++) {
            float a[4], b[4];
            *(float4*)&a[0] = *(const float4*)&As[kk][ty * 4];
            *(float4*)&b[0] = *(const float4*)&Bs[kk][tx * 4];
            #pragma unroll
            for (int i = 0; i < 4; i++)
                #pragma unroll
                for (int j = 0; j < 4; j++) acc[i][j] += a[i] * b[j];
        }
    }

    #pragma unroll
    for (int i = 0; i < 4; i++) {
        int m = m0 + ty * 4 + i;
        #pragma unroll
        for (int j = 0; j < 4; j++) {
            int n = n0 + tx * 4 + j;
            float v = acc[i][j];
            if (bias)  v += bias[n];
            if (ACT == 1) v = fmaxf(v, 0.f);
            if (resid) v += resid[(size_t)m * N + n];
            C[(size_t)m * N + n] = v;
        }
    }
}

/* --------------------- fused attention (dots+softmax+pV) ------------------ */
__global__ void attn_fused_k() {
    int b = blockIdx.y, ch = blockIdx.x;
    __shared__ float qs[8][256];     // 8 KB
    __shared__ float ps[128][8];     // 4 KB
    __shared__ float rpart[8];
    int t = threadIdx.x;
    for (int idx = t; idx < NSLOT * 256; idx += 256)
        qs[idx >> 8][idx & 255] = g_q[b * NSLOT * 256 + idx];
    if (t < 8) rpart[t] = 0.f;
    __syncthreads();

    int w = t >> 5, l = t & 31;
    const float* Kb = g_Km + ((size_t)b * NTOK + ch * 128) * 256;

    float racc = 0.f;
    for (int jj = 0; jj < 16; jj++) {
        int j = w * 16 + jj;
        float acc[8] = {0.f, 0.f, 0.f, 0.f, 0.f, 0.f, 0.f, 0.f};
        #pragma unroll
        for (int kk = 0; kk < 8; kk++) {
            float kv = Kb[(size_t)j * 256 + kk * 32 + l];
            #pragma unroll
            for (int i = 0; i < 8; i++) acc[i] += kv * qs[i][kk * 32 + l];
        }
        #pragma unroll
        for (int i = 0; i < 8; i++)
            #pragma unroll
            for (int o = 16; o; o >>= 1)
                acc[i] += __shfl_xor_sync(0xffffffffu, acc[i], o);

        float m = -1e30f;
        #pragma unroll
        for (int i = 0; i < 8; i++) m = fmaxf(m, acc[i] * SCALE);
        float e[8], sum = 0.f;
        #pragma unroll
        for (int i = 0; i < 8; i++) { e[i] = expf(acc[i] * SCALE - m); sum += e[i]; }
        float inv = 1.f / sum;
        if (l < 8) {
            float pv = 0.f;
            #pragma unroll
            for (int i = 0; i < 8; i++) pv = (l == i) ? (e[i] * inv) : pv;
            ps[j][l] = pv;
            racc += pv;
        }
    }
    if (l < 8) atomicAdd(&rpart[l], racc);
    __syncthreads();

    const float* Vb = g_Vm + ((size_t)b * NTOK + ch * 128) * 256;
    float u[8] = {0.f, 0.f, 0.f, 0.f, 0.f, 0.f, 0.f, 0.f};
    float vs = 0.f;
    for (int j = 0; j < 128; j++) {
        float vv = Vb[(size_t)j * 256 + t];
        vs += vv;
        #pragma unroll
        for (int i = 0; i < 8; i++) u[i] += ps[j][i] * vv;
    }
    float* up = g_updp + ((size_t)ch * BATCH + b) * 9 * 256;
    #pragma unroll
    for (int i = 0; i < 8; i++) up[i * 256 + t] = u[i];
    up[8 * 256 + t] = vs;
    if (t < 8) g_rp[((size_t)ch * BATCH + b) * 8 + t] = rpart[t];
}

/* updates = (sum_ch U + eps*Vsum) / (sum_ch r + 1024*eps) */
__global__ void attn_reduce_k() {
    int idx = blockIdx.x * 256 + threadIdx.x;   // 65536: [b][i][d]
    int b = idx >> 11, i = (idx >> 8) & 7, d = idx & 255;
    float s = 0.f, vs = 0.f, r = 0.f;
    #pragma unroll
    for (int ch = 0; ch < NCHUNK; ch++) {
        const float* up = g_updp + ((size_t)ch * BATCH + b) * 9 * 256;
        s  += up[i * 256 + d];
        vs += up[8 * 256 + d];
        r  += g_rp[((size_t)ch * BATCH + b) * 8 + i];
    }
    g_upd[((size_t)b * NSLOT + i) * 256 + d] =
        (s + ATTN_EPS * vs) / (r + (float)NTOK * ATTN_EPS);
}

/* GRU gate fusion, in-place on slots. */
__global__ void gru_gate_k() {
    int idx = blockIdx.x * 256 + threadIdx.x;   // 65536
    int r = idx >> 8, cc = idx & 255;
    const float* gi = g_gi + (size_t)r * 768;
    const float* gh = g_gh + (size_t)r * 768;
    float ir = gi[cc], iz = gi[256 + cc], in_ = gi[512 + cc];
    float hr = gh[cc], hz = gh[256 + cc], hn  = gh[512 + cc];
    float h  = g_slots[idx];
    float rg = 1.f / (1.f + expf(-(ir + hr)));
    float z  = 1.f / (1.f + expf(-(iz + hz)));
    float nn = tanhf(in_ + rg * hn);
    g_slots[idx] = (1.f - z) * nn + z * h;
}

/* ------------------------------- launcher --------------------------------- */
extern "C" void kernel_launch(void* const* d_in, const int* in_sizes, int n_in,
                              void* d_out, int out_size) {
    const float* inputs = (const float*)d_in[0];
    const float* noise  = (const float*)d_in[1];
    const float* mu     = (const float*)d_in[2];
    const float* lsig   = (const float*)d_in[3];
    const float* Wq     = (const float*)d_in[4];
    const float* Wk     = (const float*)d_in[5];
    const float* Wv     = (const float*)d_in[6];
    const float* wih    = (const float*)d_in[7];
    const float* whh    = (const float*)d_in[8];
    const float* bih    = (const float*)d_in[9];
    const float* bhh    = (const float*)d_in[10];
    const float* w1     = (const float*)d_in[11];
    const float* b1     = (const float*)d_in[12];
    const float* w2     = (const float*)d_in[13];
    const float* b2     = (const float*)d_in[14];
    const float* lin_g  = (const float*)d_in[15];
    const float* lin_b  = (const float*)d_in[16];
    const float* ls_g   = (const float*)d_in[17];
    const float* ls_b   = (const float*)d_in[18];
    const float* lf_g   = (const float*)d_in[19];
    const float* lf_b   = (const float*)d_in[20];

    float *pslots, *psnorm, *pq, *pupd, *pgi, *pgh, *pt1, *pt2;
    cudaGetSymbolAddress((void**)&pslots, g_slots);
    cudaGetSymbolAddress((void**)&psnorm, g_snorm);
    cudaGetSymbolAddress((void**)&pq,     g_q);
    cudaGetSymbolAddress((void**)&pupd,   g_upd);
    cudaGetSymbolAddress((void**)&pgi,    g_gi);
    cudaGetSymbolAddress((void**)&pgh,    g_gh);
    cudaGetSymbolAddress((void**)&pt1,    g_t1);
    cudaGetSymbolAddress((void**)&pt2,    g_t2);

    cudaFuncSetAttribute(kv_mma_k, cudaFuncAttributeMaxDynamicSharedMemorySize, KV_SMEM_SZ);

    /* slots = mu + exp(log_sigma) * noise */
    slots_init_k<<<ROWS, 256>>>(mu, lsig, noise);

    /* LN(x) -> bf16 hi/lo, W -> bf16 hi/lo, then HMMA K/V GEMM */
    prep_a_k<<<BATCH * NTOK, 256>>>(inputs, lin_g, lin_b);
    prep_w_k<<<512, 256>>>(Wk, Wv);
    kv_mma_k<<<dim3(4, BATCH * NTOK / 128), 256, KV_SMEM_SZ>>>();

    for (int it = 0; it < NITER; it++) {
        ln_rows_k<<<ROWS, 256>>>(pslots, psnorm, ls_g, ls_b);
        gemm_s_k<0><<<dim3(4, 4), 256>>>(psnorm, Wq, pq, 256, 256, nullptr, nullptr);

        attn_fused_k<<<dim3(NCHUNK, BATCH), 256>>>();
        attn_reduce_k<<<256, 256>>>();

        gemm_s_k<0><<<dim3(12, 4), 256>>>(pupd,   wih, pgi, 768, 256, bih, nullptr);
        gemm_s_k<0><<<dim3(12, 4), 256>>>(pslots, whh, pgh, 768, 256, bhh, nullptr);
        gru_gate_k<<<ROWS, 256>>>();

        ln_rows_k<<<ROWS, 256>>>(pslots, pt1, lf_g, lf_b);
        gemm_s_k<1><<<dim3(16, 4), 256>>>(pt1, w1, pt2, 1024, 256, b1, nullptr);
        gemm_s_k<0><<<dim3(4, 4), 256>>>(pt2, w2, pslots, 256, 1024, b2, pslots);
    }

    copy_out_k<<<ROWS, 256>>>((float*)d_out);
}

// round 12
// speedup vs baseline: 4.0848x; 1.4140x over previous
#include <cuda_runtime.h>
#include <cuda_bf16.h>
#include <math.h>
#include <stdint.h>

#define BATCH 32
#define NTOK  1024
#define CDIM  256
#define DDIM  256
#define NSLOT 8
#define ROWS  (BATCH*NSLOT)   /* 256 */
#define NITER 3
#define NCHUNK 8              /* token chunks of 128 for attention */
#define ATTN_EPS 1e-8f
#define LN_EPS   1e-5f
#define SCALE    0.0625f      /* 256^-0.5 */

/* ------------------------ scratch (device globals) ------------------------ */
__device__ __align__(256) __nv_bfloat16 g_a_hi[BATCH*NTOK*CDIM];   // LN(x) hi
__device__ __align__(256) __nv_bfloat16 g_a_lo[BATCH*NTOK*CDIM];   // LN(x) lo
__device__ __align__(256) __nv_bfloat16 g_w_hi[2*DDIM*CDIM];       // [Wk;Wv] hi
__device__ __align__(256) __nv_bfloat16 g_w_lo[2*DDIM*CDIM];       // [Wk;Wv] lo
__device__ __align__(256) float g_Km  [BATCH*NTOK*DDIM];   // keys (fp32)
__device__ __align__(256) float g_Vm  [BATCH*NTOK*DDIM];   // values (fp32)
__device__ __align__(256) float g_slots[ROWS*DDIM];
__device__ __align__(256) float g_snorm[ROWS*DDIM];
__device__ __align__(256) float g_q    [ROWS*DDIM];
__device__ __align__(256) float g_updp [NCHUNK*BATCH*9*DDIM];  // partials + Vsum; reused by mlp2 split-K
__device__ __align__(256) float g_rp   [NCHUNK*BATCH*NSLOT];   // partial rowsums
__device__ __align__(256) float g_upd  [ROWS*DDIM];
__device__ __align__(256) float g_gi   [ROWS*3*DDIM];
__device__ __align__(256) float g_gh   [ROWS*3*DDIM];
__device__ __align__(256) float g_t1   [ROWS*DDIM];
__device__ __align__(256) float g_t2   [ROWS*4*DDIM];

__device__ __forceinline__ uint32_t smem_to_u32(const void* p) {
    uint32_t a;
    asm("{ .reg .u64 t; cvta.to.shared.u64 t, %1; cvt.u32.u64 %0, t; }"
        : "=r"(a) : "l"(p));
    return a;
}

/* ------------------------------ small kernels ----------------------------- */
__global__ void slots_init_k(const float* __restrict__ mu,
                             const float* __restrict__ ls,
                             const float* __restrict__ noise) {
    int idx = blockIdx.x * 256 + threadIdx.x;      // 65536 total
    int dcol = idx & 255;
    g_slots[idx] = mu[dcol] + expf(ls[dcol]) * noise[idx];
}

__global__ void copy_out_k(float* __restrict__ out) {
    int idx = blockIdx.x * 256 + threadIdx.x;
    out[idx] = g_slots[idx];
}

/* LN(x) -> split bf16 hi/lo. One block per row. */
__global__ void prep_a_k(const float* __restrict__ in,
                         const float* __restrict__ gam, const float* __restrict__ bet) {
    int row = blockIdx.x;
    int t   = threadIdx.x;
    float x = in[(size_t)row * 256 + t];
    float s = x, ss = x * x;
    #pragma unroll
    for (int o = 16; o; o >>= 1) {
        s  += __shfl_xor_sync(0xffffffffu, s,  o);
        ss += __shfl_xor_sync(0xffffffffu, ss, o);
    }
    __shared__ float ws[8], wss[8];
    int w = t >> 5, l = t & 31;
    if (l == 0) { ws[w] = s; wss[w] = ss; }
    __syncthreads();
    if (t == 0) {
        float a = 0.f, b = 0.f;
        #pragma unroll
        for (int i = 0; i < 8; i++) { a += ws[i]; b += wss[i]; }
        ws[0] = a; wss[0] = b;
    }
    __syncthreads();
    float mean = ws[0] * (1.f / 256.f);
    float var  = wss[0] * (1.f / 256.f) - mean * mean;
    float y = (x - mean) * rsqrtf(var + LN_EPS) * gam[t] + bet[t];
    __nv_bfloat16 hi = __float2bfloat16(y);
    __nv_bfloat16 lo = __float2bfloat16(y - __bfloat162float(hi));
    g_a_hi[(size_t)row * 256 + t] = hi;
    g_a_lo[(size_t)row * 256 + t] = lo;
}

/* Wk/Wv -> split bf16 hi/lo. blockIdx.x = 0..511 rows (Wk rows then Wv rows). */
__global__ void prep_w_k(const float* __restrict__ Wk, const float* __restrict__ Wv) {
    int row = blockIdx.x;
    int t = threadIdx.x;
    const float* src = (row < 256) ? Wk : Wv;
    int n = row & 255;
    float y = src[(size_t)n * 256 + t];
    __nv_bfloat16 hi = __float2bfloat16(y);
    __nv_bfloat16 lo = __float2bfloat16(y - __bfloat162float(hi));
    g_w_hi[(size_t)row * 256 + t] = hi;
    g_w_lo[(size_t)row * 256 + t] = lo;
}

/* LayerNorm over last dim (=256), small row counts. One block per row. */
__global__ void ln_rows_k(const float* __restrict__ in, float* __restrict__ out,
                          const float* __restrict__ gam, const float* __restrict__ bet) {
    int row = blockIdx.x;
    int t   = threadIdx.x;
    float x = in[row * 256 + t];
    float s = x, ss = x * x;
    #pragma unroll
    for (int o = 16; o; o >>= 1) {
        s  += __shfl_xor_sync(0xffffffffu, s,  o);
        ss += __shfl_xor_sync(0xffffffffu, ss, o);
    }
    __shared__ float ws[8], wss[8];
    int w = t >> 5, l = t & 31;
    if (l == 0) { ws[w] = s; wss[w] = ss; }
    __syncthreads();
    if (t == 0) {
        float a = 0.f, b = 0.f;
        #pragma unroll
        for (int i = 0; i < 8; i++) { a += ws[i]; b += wss[i]; }
        ws[0] = a; wss[0] = b;
    }
    __syncthreads();
    float mean = ws[0] * (1.f / 256.f);
    float var  = wss[0] * (1.f / 256.f) - mean * mean;
    out[row * 256 + t] = (x - mean) * rsqrtf(var + LN_EPS) * gam[t] + bet[t];
}

/* -------------- K/V GEMM via mma.sync bf16 (split hi/lo, 3-term) ---------- */
/* Grid (4, 256): bx -> {mat = bx>>1 (0=K,1=V), n0 = (bx&1)*128}; by -> m0.   */
/* CTA 128x128, 8 warps (4 M x 2 N), warp tile 32x64, ldmatrix fragments.     */
#define KV_STRIDE_U 36
#define KV_TILE_U   (128*KV_STRIDE_U)     /* 4608 u32 = 18432 B */
#define KV_SMEM_SZ  (4*KV_TILE_U*4)       /* 73728 B */

#define MMA_BF16(c, a0v, a1v, a2v, a3v, b0v, b1v) \
    asm volatile("mma.sync.aligned.m16n8k16.row.col.f32.bf16.bf16.f32 " \
        "{%0,%1,%2,%3}, {%4,%5,%6,%7}, {%8,%9}, {%0,%1,%2,%3};" \
        : "+f"((c)[0]), "+f"((c)[1]), "+f"((c)[2]), "+f"((c)[3]) \
        : "r"(a0v), "r"(a1v), "r"(a2v), "r"(a3v), "r"(b0v), "r"(b1v))

#define LDSM_X4(r0, r1, r2, r3, addr) \
    asm volatile("ldmatrix.sync.aligned.m8n8.x4.shared.b16 {%0,%1,%2,%3}, [%4];" \
        : "=r"(r0), "=r"(r1), "=r"(r2), "=r"(r3) : "r"(addr))

/* load 128x64 bf16 tile (global row stride 256) into smem, stride 36 u32 */
__device__ __forceinline__ void kv_ldtile(const __nv_bfloat16* __restrict__ g,
                                          uint32_t* __restrict__ s, int t) {
    int row = t >> 1, h = t & 1;
    const uint4* src = (const uint4*)(g + (size_t)row * 256 + h * 32);
    uint4* dst = (uint4*)(s + row * KV_STRIDE_U + h * 16);
    #pragma unroll
    for (int i = 0; i < 4; i++) dst[i] = src[i];
}

__global__ __launch_bounds__(256, 2)
void kv_mma_k() {
    extern __shared__ __align__(16) uint32_t us[];
    uint32_t* uAh = us;
    uint32_t* uAl = us + KV_TILE_U;
    uint32_t* uBh = us + 2 * KV_TILE_U;
    uint32_t* uBl = us + 3 * KV_TILE_U;
    uint32_t sbase = smem_to_u32(us);

    int t = threadIdx.x, lane = t & 31, wid = t >> 5;
    int wm = wid & 3, wn = wid >> 2;        /* 4 x 2 warp grid */
    int mat = blockIdx.x >> 1;
    int n0  = (blockIdx.x & 1) * 128;
    int m0  = blockIdx.y * 128;
    int lane8 = lane & 7, lg = lane >> 3;

    const __nv_bfloat16* Ah = g_a_hi + (size_t)m0 * 256;
    const __nv_bfloat16* Al = g_a_lo + (size_t)m0 * 256;
    const __nv_bfloat16* Bh = g_w_hi + (size_t)(mat * 256 + n0) * 256;
    const __nv_bfloat16* Bl = g_w_lo + (size_t)(mat * 256 + n0) * 256;

    float acc[2][8][4];
    #pragma unroll
    for (int i = 0; i < 2; i++)
        #pragma unroll
        for (int j = 0; j < 8; j++)
            #pragma unroll
            for (int k = 0; k < 4; k++) acc[i][j][k] = 0.f;

    /* per-lane ldmatrix address components (constant across ks up to offsets) */
    /* A groups: g0:(r+0,c+0) g1:(r+8,c+0) g2:(r+0,c+4) g3:(r+8,c+4) */
    const uint32_t a_row_off = (uint32_t)((lg & 1) << 3) + lane8;
    const uint32_t a_col_off = (uint32_t)((lg >> 1) << 2);
    /* B groups: g0:(n+0,c+0) g1:(n+0,c+4) g2:(n+8,c+0) g3:(n+8,c+4) */
    const uint32_t b_row_off = (uint32_t)((lg >> 1) << 3) + lane8;
    const uint32_t b_col_off = (uint32_t)((lg & 1) << 2);

    for (int c = 0; c < 4; c++) {
        __syncthreads();
        kv_ldtile(Ah + c * 64, uAh, t);
        kv_ldtile(Al + c * 64, uAl, t);
        kv_ldtile(Bh + c * 64, uBh, t);
        kv_ldtile(Bl + c * 64, uBl, t);
        __syncthreads();

        #pragma unroll
        for (int ks = 0; ks < 4; ks++) {
            uint32_t ah[2][4], al[2][4];
            #pragma unroll
            for (int mt = 0; mt < 2; mt++) {
                uint32_t row = (uint32_t)(wm * 32 + mt * 16) + a_row_off;
                uint32_t addr = sbase + (row * KV_STRIDE_U + (uint32_t)(ks * 8) + a_col_off) * 4u;
                LDSM_X4(ah[mt][0], ah[mt][1], ah[mt][2], ah[mt][3], addr);
                LDSM_X4(al[mt][0], al[mt][1], al[mt][2], al[mt][3],
                        addr + KV_TILE_U * 4u);
            }
            #pragma unroll
            for (int nb = 0; nb < 8; nb += 2) {
                uint32_t brow = (uint32_t)(wn * 64 + nb * 8) + b_row_off;
                uint32_t baddr = sbase + 2u * KV_TILE_U * 4u +
                                 (brow * KV_STRIDE_U + (uint32_t)(ks * 8) + b_col_off) * 4u;
                uint32_t bh0, bh1, bh2, bh3, bl0, bl1, bl2, bl3;
                LDSM_X4(bh0, bh1, bh2, bh3, baddr);
                LDSM_X4(bl0, bl1, bl2, bl3, baddr + KV_TILE_U * 4u);
                #pragma unroll
                for (int mt = 0; mt < 2; mt++) {
                    MMA_BF16(acc[mt][nb],   ah[mt][0], ah[mt][1], ah[mt][2], ah[mt][3], bh0, bh1);
                    MMA_BF16(acc[mt][nb],   al[mt][0], al[mt][1], al[mt][2], al[mt][3], bh0, bh1);
                    MMA_BF16(acc[mt][nb],   ah[mt][0], ah[mt][1], ah[mt][2], ah[mt][3], bl0, bl1);
                    MMA_BF16(acc[mt][nb+1], ah[mt][0], ah[mt][1], ah[mt][2], ah[mt][3], bh2, bh3);
                    MMA_BF16(acc[mt][nb+1], al[mt][0], al[mt][1], al[mt][2], al[mt][3], bh2, bh3);
                    MMA_BF16(acc[mt][nb+1], ah[mt][0], ah[mt][1], ah[mt][2], ah[mt][3], bl2, bl3);
                }
            }
        }
    }

    float* C = (mat == 0) ? g_Km : g_Vm;
    #pragma unroll
    for (int mt = 0; mt < 2; mt++) {
        #pragma unroll
        for (int nt = 0; nt < 8; nt++) {
            int row = m0 + wm * 32 + mt * 16 + (lane >> 2);
            int col = n0 + wn * 64 + nt * 8 + (lane & 3) * 2;
            float2 v0 = make_float2(acc[mt][nt][0], acc[mt][nt][1]);
            float2 v1 = make_float2(acc[mt][nt][2], acc[mt][nt][3]);
            *(float2*)&C[(size_t)row * 256 + col]       = v0;
            *(float2*)&C[(size_t)(row + 8) * 256 + col] = v1;
        }
    }
}

/* ------------------------- small GEMM (64x64x32) -------------------------- */
/* C[M=256,N] = act(A @ Bw^T + bias) + resid */
template<int ACT>
__global__ __launch_bounds__(256)
void gemm_s_k(const float* __restrict__ A, const float* __restrict__ Bw,
              float* __restrict__ C, int N, int K,
              const float* __restrict__ bias, const float* __restrict__ resid) {
    __shared__ float As[32][64];
    __shared__ float Bs[32][64];
    const int tid = threadIdx.x;
    const int n0 = blockIdx.x * 64, m0 = blockIdx.y * 64;
    const int lrow = tid >> 2, lcol = (tid & 3) * 8;
    const int tx = tid & 15, ty = tid >> 4;

    float acc[4][4];
    #pragma unroll
    for (int i = 0; i < 4; i++)
        #pragma unroll
        for (int j = 0; j < 4; j++) acc[i][j] = 0.f;

    const float* Ar = A  + (size_t)(m0 + lrow) * K;
    const float* Br = Bw + (size_t)(n0 + lrow) * K;

    for (int k0 = 0; k0 < K; k0 += 32) {
        float4 a0 = *(const float4*)(Ar + k0 + lcol);
        float4 a1 = *(const float4*)(Ar + k0 + lcol + 4);
        float4 b0 = *(const float4*)(Br + k0 + lcol);
        float4 b1 = *(const float4*)(Br + k0 + lcol + 4);
        __syncthreads();
        As[lcol + 0][lrow] = a0.x; As[lcol + 1][lrow] = a0.y;
        As[lcol + 2][lrow] = a0.z; As[lcol + 3][lrow] = a0.w;
        As[lcol + 4][lrow] = a1.x; As[lcol + 5][lrow] = a1.y;
        As[lcol + 6][lrow] = a1.z; As[lcol + 7][lrow] = a1.w;
        Bs[lcol + 0][lrow] = b0.x; Bs[lcol + 1][lrow] = b0.y;
        Bs[lcol + 2][lrow] = b0.z; Bs[lcol + 3][lrow] = b0.w;
        Bs[lcol + 4][lrow] = b1.x; Bs[lcol + 5][lrow] = b1.y;
        Bs[lcol + 6][lrow] = b1.z; Bs[lcol + 7][lrow] = b1.w;
        __syncthreads();
        #pragma unroll
        for (int kk = 0; kk < 32; kk++) {
            float a[4], b[4];
            *(float4*)&a[0] = *(const float4*)&As[kk][ty * 4];
            *(float4*)&b[0] = *(const float4*)&Bs[kk][tx * 4];
            #pragma unroll
            for (int i = 0; i < 4; i++)
                #pragma unroll
                for (int j = 0; j < 4; j++) acc[i][j] += a[i] * b[j];
        }
    }

    #pragma unroll
    for (int i = 0; i < 4; i++) {
        int m = m0 + ty * 4 + i;
        #pragma unroll
        for (int j = 0; j < 4; j++) {
            int n = n0 + tx * 4 + j;
            float v = acc[i][j];
            if (bias)  v += bias[n];
            if (ACT == 1) v = fmaxf(v, 0.f);
            if (resid) v += resid[(size_t)m * N + n];
            C[(size_t)m * N + n] = v;
        }
    }
}

/* ------- fused GRU gates GEMM: z=0 -> gi = upd@wih^T+bih, z=1 -> gh ------- */
__global__ __launch_bounds__(256)
void gemm_gru_k(const float* __restrict__ upd, const float* __restrict__ wih,
                const float* __restrict__ bih,
                const float* __restrict__ slots_, const float* __restrict__ whh,
                const float* __restrict__ bhh) {
    const float* A    = blockIdx.z ? slots_ : upd;
    const float* Bw   = blockIdx.z ? whh : wih;
    const float* bias = blockIdx.z ? bhh : bih;
    float* C          = blockIdx.z ? g_gh : g_gi;
    const int N = 768, K = 256;

    __shared__ float As[32][64];
    __shared__ float Bs[32][64];
    const int tid = threadIdx.x;
    const int n0 = blockIdx.x * 64, m0 = blockIdx.y * 64;
    const int lrow = tid >> 2, lcol = (tid & 3) * 8;
    const int tx = tid & 15, ty = tid >> 4;

    float acc[4][4];
    #pragma unroll
    for (int i = 0; i < 4; i++)
        #pragma unroll
        for (int j = 0; j < 4; j++) acc[i][j] = 0.f;

    const float* Ar = A  + (size_t)(m0 + lrow) * K;
    const float* Br = Bw + (size_t)(n0 + lrow) * K;

    for (int k0 = 0; k0 < K; k0 += 32) {
        float4 a0 = *(const float4*)(Ar + k0 + lcol);
        float4 a1 = *(const float4*)(Ar + k0 + lcol + 4);
        float4 b0 = *(const float4*)(Br + k0 + lcol);
        float4 b1 = *(const float4*)(Br + k0 + lcol + 4);
        __syncthreads();
        As[lcol + 0][lrow] = a0.x; As[lcol + 1][lrow] = a0.y;
        As[lcol + 2][lrow] = a0.z; As[lcol + 3][lrow] = a0.w;
        As[lcol + 4][lrow] = a1.x; As[lcol + 5][lrow] = a1.y;
        As[lcol + 6][lrow] = a1.z; As[lcol + 7][lrow] = a1.w;
        Bs[lcol + 0][lrow] = b0.x; Bs[lcol + 1][lrow] = b0.y;
        Bs[lcol + 2][lrow] = b0.z; Bs[lcol + 3][lrow] = b0.w;
        Bs[lcol + 4][lrow] = b1.x; Bs[lcol + 5][lrow] = b1.y;
        Bs[lcol + 6][lrow] = b1.z; Bs[lcol + 7][lrow] = b1.w;
        __syncthreads();
        #pragma unroll
        for (int kk = 0; kk < 32; kk++) {
            float a[4], b[4];
            *(float4*)&a[0] = *(const float4*)&As[kk][ty * 4];
            *(float4*)&b[0] = *(const float4*)&Bs[kk][tx * 4];
            #pragma unroll
            for (int i = 0; i < 4; i++)
                #pragma unroll
                for (int j = 0; j < 4; j++) acc[i][j] += a[i] * b[j];
        }
    }

    #pragma unroll
    for (int i = 0; i < 4; i++) {
        int m = m0 + ty * 4 + i;
        #pragma unroll
        for (int j = 0; j < 4; j++) {
            int n = n0 + tx * 4 + j;
            C[(size_t)m * N + n] = acc[i][j] + bias[n];
        }
    }
}

/* ---------- mlp2 split-K: partials over 4 K-chunks of 256 (K=1024) -------- */
/* grid (4 nblk, 4 mblk, 4 kc); partials in g_updp[kc*65536 + m*256+n].       */
__global__ __launch_bounds__(256)
void mlp2_part_k(const float* __restrict__ w2) {
    const float* A = g_t2;          /* [256, 1024] */
    const int N = 256, K = 1024;
    const int kc = blockIdx.z;

    __shared__ float As[32][64];
    __shared__ float Bs[32][64];
    const int tid = threadIdx.x;
    const int n0 = blockIdx.x * 64, m0 = blockIdx.y * 64;
    const int lrow = tid >> 2, lcol = (tid & 3) * 8;
    const int tx = tid & 15, ty = tid >> 4;

    float acc[4][4];
    #pragma unroll
    for (int i = 0; i < 4; i++)
        #pragma unroll
        for (int j = 0; j < 4; j++) acc[i][j] = 0.f;

    const float* Ar = A  + (size_t)(m0 + lrow) * K;
    const float* Br = w2 + (size_t)(n0 + lrow) * K;

    for (int k0 = kc * 256; k0 < kc * 256 + 256; k0 += 32) {
        float4 a0 = *(const float4*)(Ar + k0 + lcol);
        float4 a1 = *(const float4*)(Ar + k0 + lcol + 4);
        float4 b0 = *(const float4*)(Br + k0 + lcol);
        float4 b1 = *(const float4*)(Br + k0 + lcol + 4);
        __syncthreads();
        As[lcol + 0][lrow] = a0.x; As[lcol + 1][lrow] = a0.y;
        As[lcol + 2][lrow] = a0.z; As[lcol + 3][lrow] = a0.w;
        As[lcol + 4][lrow] = a1.x; As[lcol + 5][lrow] = a1.y;
        As[lcol + 6][lrow] = a1.z; As[lcol + 7][lrow] = a1.w;
        Bs[lcol + 0][lrow] = b0.x; Bs[lcol + 1][lrow] = b0.y;
        Bs[lcol + 2][lrow] = b0.z; Bs[lcol + 3][lrow] = b0.w;
        Bs[lcol + 4][lrow] = b1.x; Bs[lcol + 5][lrow] = b1.y;
        Bs[lcol + 6][lrow] = b1.z; Bs[lcol + 7][lrow] = b1.w;
        __syncthreads();
        #pragma unroll
        for (int kk = 0; kk < 32; kk++) {
            float a[4], b[4];
            *(float4*)&a[0] = *(const float4*)&As[kk][ty * 4];
            *(float4*)&b[0] = *(const float4*)&Bs[kk][tx * 4];
            #pragma unroll
            for (int i = 0; i < 4; i++)
                #pragma unroll
                for (int j = 0; j < 4; j++) acc[i][j] += a[i] * b[j];
        }
    }

    float* part = g_updp + (size_t)kc * 65536;
    #pragma unroll
    for (int i = 0; i < 4; i++) {
        int m = m0 + ty * 4 + i;
        #pragma unroll
        for (int j = 0; j < 4; j++) {
            int n = n0 + tx * 4 + j;
            part[(size_t)m * N + n] = acc[i][j];
        }
    }
}

/* slots += b2 + sum_kc partial (deterministic fixed-order reduce) */
__global__ void mlp2_red_k(const float* __restrict__ b2) {
    int idx = blockIdx.x * 256 + threadIdx.x;   // 65536
    int n = idx & 255;
    float v = g_slots[idx] + b2[n];
    v += g_updp[idx];
    v += g_updp[65536 + idx];
    v += g_updp[2 * 65536 + idx];
    v += g_updp[3 * 65536 + idx];
    g_slots[idx] = v;
}

/* --------------------- fused attention (dots+softmax+pV) ------------------ */
__global__ void attn_fused_k() {
    int b = blockIdx.y, ch = blockIdx.x;
    __shared__ float qs[8][256];     // 8 KB
    __shared__ float ps[128][8];     // 4 KB
    __shared__ float rpart[8];
    int t = threadIdx.x;
    for (int idx = t; idx < NSLOT * 256; idx += 256)
        qs[idx >> 8][idx & 255] = g_q[b * NSLOT * 256 + idx];
    if (t < 8) rpart[t] = 0.f;
    __syncthreads();

    int w = t >> 5, l = t & 31;
    const float* Kb = g_Km + ((size_t)b * NTOK + ch * 128) * 256;

    float racc = 0.f;
    for (int jj = 0; jj < 16; jj++) {
        int j = w * 16 + jj;
        float acc[8] = {0.f, 0.f, 0.f, 0.f, 0.f, 0.f, 0.f, 0.f};
        #pragma unroll
        for (int kk = 0; kk < 8; kk++) {
            float kv = Kb[(size_t)j * 256 + kk * 32 + l];
            #pragma unroll
            for (int i = 0; i < 8; i++) acc[i] += kv * qs[i][kk * 32 + l];
        }
        #pragma unroll
        for (int i = 0; i < 8; i++)
            #pragma unroll
            for (int o = 16; o; o >>= 1)
                acc[i] += __shfl_xor_sync(0xffffffffu, acc[i], o);

        float m = -1e30f;
        #pragma unroll
        for (int i = 0; i < 8; i++) m = fmaxf(m, acc[i] * SCALE);
        float e[8], sum = 0.f;
        #pragma unroll
        for (int i = 0; i < 8; i++) { e[i] = expf(acc[i] * SCALE - m); sum += e[i]; }
        float inv = 1.f / sum;
        if (l < 8) {
            float pv = 0.f;
            #pragma unroll
            for (int i = 0; i < 8; i++) pv = (l == i) ? (e[i] * inv) : pv;
            ps[j][l] = pv;
            racc += pv;
        }
    }
    if (l < 8) atomicAdd(&rpart[l], racc);
    __syncthreads();

    const float* Vb = g_Vm + ((size_t)b * NTOK + ch * 128) * 256;
    float u[8] = {0.f, 0.f, 0.f, 0.f, 0.f, 0.f, 0.f, 0.f};
    float vs = 0.f;
    for (int j = 0; j < 128; j++) {
        float vv = Vb[(size_t)j * 256 + t];
        vs += vv;
        #pragma unroll
        for (int i = 0; i < 8; i++) u[i] += ps[j][i] * vv;
    }
    float* up = g_updp + ((size_t)ch * BATCH + b) * 9 * 256;
    #pragma unroll
    for (int i = 0; i < 8; i++) up[i * 256 + t] = u[i];
    up[8 * 256 + t] = vs;
    if (t < 8) g_rp[((size_t)ch * BATCH + b) * 8 + t] = rpart[t];
}

/* updates = (sum_ch U + eps*Vsum) / (sum_ch r + 1024*eps) */
__global__ void attn_reduce_k() {
    int idx = blockIdx.x * 256 + threadIdx.x;   // 65536: [b][i][d]
    int b = idx >> 11, i = (idx >> 8) & 7, d = idx & 255;
    float s = 0.f, vs = 0.f, r = 0.f;
    #pragma unroll
    for (int ch = 0; ch < NCHUNK; ch++) {
        const float* up = g_updp + ((size_t)ch * BATCH + b) * 9 * 256;
        s  += up[i * 256 + d];
        vs += up[8 * 256 + d];
        r  += g_rp[((size_t)ch * BATCH + b) * 8 + i];
    }
    g_upd[((size_t)b * NSLOT + i) * 256 + d] =
        (s + ATTN_EPS * vs) / (r + (float)NTOK * ATTN_EPS);
}

/* GRU gate fusion, in-place on slots. */
__global__ void gru_gate_k() {
    int idx = blockIdx.x * 256 + threadIdx.x;   // 65536
    int r = idx >> 8, cc = idx & 255;
    const float* gi = g_gi + (size_t)r * 768;
    const float* gh = g_gh + (size_t)r * 768;
    float ir = gi[cc], iz = gi[256 + cc], in_ = gi[512 + cc];
    float hr = gh[cc], hz = gh[256 + cc], hn  = gh[512 + cc];
    float h  = g_slots[idx];
    float rg = 1.f / (1.f + expf(-(ir + hr)));
    float z  = 1.f / (1.f + expf(-(iz + hz)));
    float nn = tanhf(in_ + rg * hn);
    g_slots[idx] = (1.f - z) * nn + z * h;
}

/* ------------------------------- launcher --------------------------------- */
extern "C" void kernel_launch(void* const* d_in, const int* in_sizes, int n_in,
                              void* d_out, int out_size) {
    const float* inputs = (const float*)d_in[0];
    const float* noise  = (const float*)d_in[1];
    const float* mu     = (const float*)d_in[2];
    const float* lsig   = (const float*)d_in[3];
    const float* Wq     = (const float*)d_in[4];
    const float* Wk     = (const float*)d_in[5];
    const float* Wv     = (const float*)d_in[6];
    const float* wih    = (const float*)d_in[7];
    const float* whh    = (const float*)d_in[8];
    const float* bih    = (const float*)d_in[9];
    const float* bhh    = (const float*)d_in[10];
    const float* w1     = (const float*)d_in[11];
    const float* b1     = (const float*)d_in[12];
    const float* w2     = (const float*)d_in[13];
    const float* b2     = (const float*)d_in[14];
    const float* lin_g  = (const float*)d_in[15];
    const float* lin_b  = (const float*)d_in[16];
    const float* ls_g   = (const float*)d_in[17];
    const float* ls_b   = (const float*)d_in[18];
    const float* lf_g   = (const float*)d_in[19];
    const float* lf_b   = (const float*)d_in[20];

    float *pslots, *psnorm, *pq, *pupd, *pt1, *pt2;
    cudaGetSymbolAddress((void**)&pslots, g_slots);
    cudaGetSymbolAddress((void**)&psnorm, g_snorm);
    cudaGetSymbolAddress((void**)&pq,     g_q);
    cudaGetSymbolAddress((void**)&pupd,   g_upd);
    cudaGetSymbolAddress((void**)&pt1,    g_t1);
    cudaGetSymbolAddress((void**)&pt2,    g_t2);

    cudaFuncSetAttribute(kv_mma_k, cudaFuncAttributeMaxDynamicSharedMemorySize, KV_SMEM_SZ);

    /* slots = mu + exp(log_sigma) * noise */
    slots_init_k<<<ROWS, 256>>>(mu, lsig, noise);

    /* LN(x) -> bf16 hi/lo, W -> bf16 hi/lo, then HMMA K/V GEMM */
    prep_a_k<<<BATCH * NTOK, 256>>>(inputs, lin_g, lin_b);
    prep_w_k<<<512, 256>>>(Wk, Wv);
    kv_mma_k<<<dim3(4, BATCH * NTOK / 128), 256, KV_SMEM_SZ>>>();

    for (int it = 0; it < NITER; it++) {
        ln_rows_k<<<ROWS, 256>>>(pslots, psnorm, ls_g, ls_b);
        gemm_s_k<0><<<dim3(4, 4), 256>>>(psnorm, Wq, pq, 256, 256, nullptr, nullptr);

        attn_fused_k<<<dim3(NCHUNK, BATCH), 256>>>();
        attn_reduce_k<<<256, 256>>>();

        gemm_gru_k<<<dim3(12, 4, 2), 256>>>(pupd, wih, bih, pslots, whh, bhh);
        gru_gate_k<<<ROWS, 256>>>();

        ln_rows_k<<<ROWS, 256>>>(pslots, pt1, lf_g, lf_b);
        gemm_s_k<1><<<dim3(16, 4), 256>>>(pt1, w1, pt2, 1024, 256, b1, nullptr);
        mlp2_part_k<<<dim3(4, 4, 4), 256>>>(w2);
        mlp2_red_k<<<256, 256>>>(b2);
    }

    copy_out_k<<<ROWS, 256>>>((float*)d_out);
}